// round 16
// baseline (speedup 1.0000x reference)
#include <cuda_runtime.h>
#include <cuda_bf16.h>
#include <math.h>
#include <stdint.h>

#define NPTS   65536
#define NN     34
#define KP     15
#define INF    64
#define OUTF   64
#define EXTENTF 0.5f
#define KW2    512                // u32 words per A/B row (bf16 pairs), K'=1024 (i' = c*16+k, k=15 pad)
#define MT     64                 // points per fused CTA
#define NFUSE  (NPTS / MT)        // 1024 fused CTAs
#define NCHUNK 16                 // 1024 / 64

// fused smem: double-buffered GEMM tiles (A1,B1,B2; A2 read via LDG frags) + gather scratch
#define AS      144
#define OFS_A1  0
#define OFS_B1  9216
#define OFS_B2  18432
#define BUFSZ   27648
#define SW_OFF  (2 * BUFSZ)               // s_w: 8 warps x 34 rows x 16 floats = 17408 B
#define DKP_OFF (SW_OFF + 17408)          // s_dkp: 8 x 15 x 4 floats = 1920 B
#define SM_FUSE (DKP_OFF + 1920)          // 74624 B

typedef unsigned long long u64;
typedef unsigned int u32;

// ---------------- device scratch ----------------
__device__ __align__(16) u32 g_A1[NPTS * KW2];    // wf hi  (bf16 pairs, i' = c*16+k)
__device__ __align__(16) u32 g_A2[NPTS * KW2];    // wf residual
__device__ __align__(16) u32 g_OB1[64 * KW2];     // offset_weight^T hi [d][i'] pairs
__device__ __align__(16) u32 g_OB2[64 * KW2];
__device__ __align__(16) u32 g_WB1[64 * KW2];     // weight^T hi [o][i'] pairs
__device__ __align__(16) u32 g_WB2[64 * KW2];
__device__ __align__(16) float g_dkp[NPTS * KP * 4];  // deformed kp xyz + modulation
__device__ float g_psum  [NFUSE * OUTF];
__device__ float g_psumsq[NFUSE * OUTF];
__device__ __align__(16) float g_scale[OUTF];
__device__ __align__(16) float g_shift[OUTF];

// ---------------- helpers ----------------
__device__ __forceinline__ void f2fma(float2 &acc, float2 a, float2 b) {
    asm("{\n\t"
        ".reg .b64 ra, rb, rc;\n\t"
        "mov.b64 ra, {%2, %3};\n\t"
        "mov.b64 rb, {%4, %5};\n\t"
        "mov.b64 rc, {%0, %1};\n\t"
        "fma.rn.f32x2 rc, ra, rb, rc;\n\t"
        "mov.b64 {%0, %1}, rc;\n\t"
        "}"
        : "+f"(acc.x), "+f"(acc.y)
        : "f"(a.x), "f"(a.y), "f"(b.x), "f"(b.y));
}

__device__ __forceinline__ uint32_t smem_u32(const void* p) {
    uint32_t a;
    asm("{ .reg .u64 t; cvta.to.shared.u64 t, %1; cvt.u32.u64 %0, t; }" : "=r"(a) : "l"(p));
    return a;
}

#define CP_ASYNC16(dst, src)                                                      \
    asm volatile("{ .reg .u64 g; cvta.to.global.u64 g, %1; "                      \
                 "cp.async.cg.shared.global [%0], [g], 16; }"                     \
                 :: "r"(dst), "l"(src) : "memory")
#define CP_COMMIT() asm volatile("cp.async.commit_group;" ::: "memory")
#define CP_WAIT0()  asm volatile("cp.async.wait_group 0;" ::: "memory")

#define LDSM_X4(r, addr)                                                          \
    asm volatile("ldmatrix.sync.aligned.m8n8.x4.shared.b16 {%0,%1,%2,%3}, [%4];"  \
        : "=r"((r)[0]), "=r"((r)[1]), "=r"((r)[2]), "=r"((r)[3]) : "r"(addr))

#define MMA_BF16(d, a, b0, b1)                                                    \
    asm volatile("mma.sync.aligned.m16n8k16.row.col.f32.bf16.bf16.f32 "           \
        "{%0,%1,%2,%3}, {%4,%5,%6,%7}, {%8,%9}, {%0,%1,%2,%3};"                   \
        : "+f"((d)[0]), "+f"((d)[1]), "+f"((d)[2]), "+f"((d)[3])                  \
        : "r"((a)[0]), "r"((a)[1]), "r"((a)[2]), "r"((a)[3]), "r"(b0), "r"(b1))

__device__ __forceinline__ u32 pack_bf16(float lo, float hi) {
    __nv_bfloat162 h = __floats2bfloat162_rn(lo, hi);
    return *(u32*)&h;
}
__device__ __forceinline__ float bf16_res(float v) {
    return v - __bfloat162float(__float2bfloat16_rn(v));
}

// ---------------- prep: hi/lo bf16 transposed weight matrices, i' = c*16+k order ----------------
__global__ void prep_kernel(const float* __restrict__ ow, const float* __restrict__ w) {
    int t = blockIdx.x * blockDim.x + threadIdx.x;
    int stride = gridDim.x * blockDim.x;
    for (int idx = t; idx < 64 * KW2; idx += stride) {
        int row = idx / KW2, j = idx - row * KW2;
        int ip0 = 2 * j, ip1 = 2 * j + 1;
        int c0 = ip0 >> 4, k0 = ip0 & 15;
        int c1 = ip1 >> 4, k1 = ip1 & 15;
        float v0 = (k0 < 15 && row < 60) ? ow[(k0 * 64 + c0) * 60 + row] : 0.f;
        float v1 = (k1 < 15 && row < 60) ? ow[(k1 * 64 + c1) * 60 + row] : 0.f;
        g_OB1[idx] = pack_bf16(v0, v1);
        g_OB2[idx] = pack_bf16(bf16_res(v0), bf16_res(v1));
        float u0 = (k0 < 15) ? w[(k0 * 64 + c0) * 64 + row] : 0.f;
        float u1 = (k1 < 15) ? w[(k1 * 64 + c1) * 64 + row] : 0.f;
        g_WB1[idx] = pack_bf16(u0, u1);
        g_WB2[idx] = pack_bf16(bf16_res(u0), bf16_res(u1));
    }
}

// ---------------- gather FMA block: 16 FFMA2 on one weight row ----------------
#define WROW16(a_cur, f_cur) do {                                                \
    float2 ff0 = make_float2((f_cur).x, (f_cur).x);                              \
    float2 ff1 = make_float2((f_cur).y, (f_cur).y);                              \
    const float4* wr = (const float4*)&s_w[wid * 34 * 16 + (a_cur) * 16];        \
    float4 w0 = wr[0], w1 = wr[1], w2 = wr[2], w3 = wr[3];                       \
    f2fma(acc[0][0], make_float2(w0.x, w0.y), ff0);                              \
    f2fma(acc[0][1], make_float2(w0.x, w0.y), ff1);                              \
    f2fma(acc[1][0], make_float2(w0.z, w0.w), ff0);                              \
    f2fma(acc[1][1], make_float2(w0.z, w0.w), ff1);                              \
    f2fma(acc[2][0], make_float2(w1.x, w1.y), ff0);                              \
    f2fma(acc[2][1], make_float2(w1.x, w1.y), ff1);                              \
    f2fma(acc[3][0], make_float2(w1.z, w1.w), ff0);                              \
    f2fma(acc[3][1], make_float2(w1.z, w1.w), ff1);                              \
    f2fma(acc[4][0], make_float2(w2.x, w2.y), ff0);                              \
    f2fma(acc[4][1], make_float2(w2.x, w2.y), ff1);                              \
    f2fma(acc[5][0], make_float2(w2.z, w2.w), ff0);                              \
    f2fma(acc[5][1], make_float2(w2.z, w2.w), ff1);                              \
    f2fma(acc[6][0], make_float2(w3.x, w3.y), ff0);                              \
    f2fma(acc[6][1], make_float2(w3.x, w3.y), ff1);                              \
    f2fma(acc[7][0], make_float2(w3.z, w3.w), ff0);                              \
    f2fma(acc[7][1], make_float2(w3.z, w3.w), ff1);                              \
} while (0)

// sparse gather loop over ballot mask (warp-uniform), 1-deep prefetch, shfl idx
#define SPARSE_GATHER_LOOP(mask) do {                                            \
    u64 m_ = (mask);                                                             \
    int a_nx = -1; float2 f_nx = make_float2(0.f, 0.f);                          \
    if (m_) {                                                                    \
        a_nx = __ffsll((long long)m_) - 1; m_ &= m_ - 1;                         \
        int id_ = (a_nx < 32) ? __shfl_sync(0xffffffffu, idA, a_nx)              \
                              : __shfl_sync(0xffffffffu, idB, a_nx - 32);        \
        f_nx = *(const float2*)&feat[(size_t)id_ * INF + 2 * lane];              \
    }                                                                            \
    while (a_nx >= 0) {                                                          \
        int a_cur = a_nx; float2 f_cur = f_nx;                                   \
        if (m_) {                                                                \
            a_nx = __ffsll((long long)m_) - 1; m_ &= m_ - 1;                     \
            int id_ = (a_nx < 32) ? __shfl_sync(0xffffffffu, idA, a_nx)          \
                                  : __shfl_sync(0xffffffffu, idB, a_nx - 32);    \
            f_nx = *(const float2*)&feat[(size_t)id_ * INF + 2 * lane];          \
        } else a_nx = -1;                                                        \
        WROW16(a_cur, f_cur);                                                    \
    }                                                                            \
} while (0)

// direct bf16 hi/res pack + store: lane writes 8 pairs per channel (c = 2*lane+h)
#define STORE_A(nn) do {                                                         \
    _Pragma("unroll")                                                            \
    for (int h = 0; h < 2; h++) {                                                \
        int c = 2 * lane + h;                                                    \
        u32 base = (u32)(nn) * KW2 + (u32)c * 8;                                 \
        uint4 hi0, hi1, lo0, lo1;                                                \
        hi0.x = pack_bf16(acc[0][h].x, acc[0][h].y);                             \
        hi0.y = pack_bf16(acc[1][h].x, acc[1][h].y);                             \
        hi0.z = pack_bf16(acc[2][h].x, acc[2][h].y);                             \
        hi0.w = pack_bf16(acc[3][h].x, acc[3][h].y);                             \
        hi1.x = pack_bf16(acc[4][h].x, acc[4][h].y);                             \
        hi1.y = pack_bf16(acc[5][h].x, acc[5][h].y);                             \
        hi1.z = pack_bf16(acc[6][h].x, acc[6][h].y);                             \
        hi1.w = pack_bf16(acc[7][h].x, acc[7][h].y);                             \
        lo0.x = pack_bf16(bf16_res(acc[0][h].x), bf16_res(acc[0][h].y));         \
        lo0.y = pack_bf16(bf16_res(acc[1][h].x), bf16_res(acc[1][h].y));         \
        lo0.z = pack_bf16(bf16_res(acc[2][h].x), bf16_res(acc[2][h].y));         \
        lo0.w = pack_bf16(bf16_res(acc[3][h].x), bf16_res(acc[3][h].y));         \
        lo1.x = pack_bf16(bf16_res(acc[4][h].x), bf16_res(acc[4][h].y));         \
        lo1.y = pack_bf16(bf16_res(acc[5][h].x), bf16_res(acc[5][h].y));         \
        lo1.z = pack_bf16(bf16_res(acc[6][h].x), bf16_res(acc[6][h].y));         \
        lo1.w = pack_bf16(bf16_res(acc[7][h].x), bf16_res(acc[7][h].y));         \
        *(uint4*)&g_A1[base]     = hi0;                                          \
        *(uint4*)&g_A1[base + 4] = hi1;                                          \
        *(uint4*)&g_A2[base]     = lo0;                                          \
        *(uint4*)&g_A2[base + 4] = lo1;                                          \
    }                                                                            \
} while (0)

// ---------------- GEMM staging: cp.async one K-chunk (A1, B1, B2) ----------------
__device__ __forceinline__ void stage_chunk(const u32* __restrict__ B1g,
                                            const u32* __restrict__ B2g,
                                            int c, uint32_t smb, int buf,
                                            int tid, int pt0) {
    uint32_t base = smb + (uint32_t)buf * BUFSZ;
    #pragma unroll
    for (int it = 0; it < 2; it++) {
        int u = it * 256 + tid;
        int r = u >> 3, q = u & 7;
        uint32_t d = base + (uint32_t)(r * AS + q * 16);
        CP_ASYNC16(d + OFS_A1, g_A1 + (size_t)(pt0 + r) * KW2 + c * 32 + q * 4);
        CP_ASYNC16(d + OFS_B1, B1g + r * KW2 + c * 32 + q * 4);
        CP_ASYNC16(d + OFS_B2, B2g + r * KW2 + c * 32 + q * 4);
    }
}

// ---------------- fused GEMM phase: D[64 x 64] = A[64 x 1024] * B[64 x 1024]^T ----------------
// 8 warps = 4 (M16) x 2 (N32). A2 residual read as LDG fragments (L2 hits).
__device__ __forceinline__ void run_gemm_fused(const u32* __restrict__ B1g,
                                               const u32* __restrict__ B2g,
                                               char* smem, float* acc) {
    const int tid  = threadIdx.x;
    const int wid  = tid >> 5;
    const int lane = tid & 31;
    const int wm   = wid & 3;
    const int wn   = wid >> 2;
    const int pt0  = blockIdx.x * MT;
    const uint32_t smb = smem_u32(smem);

    const uint32_t aoff = (uint32_t)(wm * 16 + (lane & 15)) * AS + ((lane >> 4) << 4);
    const uint32_t brow = (uint32_t)(((lane >> 4) << 3) + (lane & 7));
    const uint32_t boff = (uint32_t)(wn * 32) * AS + brow * AS + (((lane >> 3) & 1) << 4);
    const u32* a2p = g_A2 + (size_t)(pt0 + wm * 16 + (lane >> 2)) * KW2 + (lane & 3);

    #pragma unroll
    for (int i = 0; i < 16; i++) acc[i] = 0.f;

    stage_chunk(B1g, B2g, 0, smb, 0, tid, pt0);
    CP_COMMIT();

    int buf = 0;
    #pragma unroll 1
    for (int c = 0; c < NCHUNK; c++) {
        CP_WAIT0();
        __syncthreads();
        if (c + 1 < NCHUNK) {
            stage_chunk(B1g, B2g, c + 1, smb, buf ^ 1, tid, pt0);
            CP_COMMIT();
        }
        const uint32_t base = smb + (uint32_t)buf * BUFSZ;
        const uint32_t a1b = base + OFS_A1;
        const uint32_t b1b = base + OFS_B1, b2b = base + OFS_B2;

        #pragma unroll
        for (int ks = 0; ks < 4; ks++) {
            const uint32_t kb = (uint32_t)(ks * 32);
            uint32_t a1[4], a2[4];
            LDSM_X4(a1, a1b + aoff + kb);
            {
                const u32* p2 = a2p + c * 32 + ks * 8;
                a2[0] = p2[0];
                a2[1] = p2[8 * KW2];
                a2[2] = p2[4];
                a2[3] = p2[8 * KW2 + 4];
            }
            #pragma unroll
            for (int nb2 = 0; nb2 < 2; nb2++) {
                uint32_t b1[4], b2[4];
                uint32_t bo = (uint32_t)(nb2 * 16) * AS + boff + kb;
                LDSM_X4(b1, b1b + bo);
                LDSM_X4(b2, b2b + bo);
                float* d0 = acc + nb2 * 8;
                float* d1 = acc + nb2 * 8 + 4;
                MMA_BF16(d0, a1, b1[0], b1[1]);
                MMA_BF16(d1, a1, b1[2], b1[3]);
                MMA_BF16(d0, a1, b2[0], b2[1]);
                MMA_BF16(d1, a1, b2[2], b2[3]);
                MMA_BF16(d0, a2, b1[0], b1[1]);
                MMA_BF16(d1, a2, b1[2], b1[3]);
            }
        }
        buf ^= 1;
    }
    __syncthreads();   // all warps done with tiles before epilogue reuse
}

// store acc -> sx[64][68] staging (aliases tile region)
__device__ __forceinline__ void acc_to_smem(float* sx, const float* acc) {
    const int tid  = threadIdx.x;
    const int wid  = tid >> 5;
    const int lane = tid & 31;
    const int wm   = wid & 3;
    const int wn   = wid >> 2;
    int r0 = wm * 16 + (lane >> 2);
    int cb = (lane & 3) * 2;
    #pragma unroll
    for (int nb2 = 0; nb2 < 2; nb2++) {
        #pragma unroll
        for (int h = 0; h < 2; h++) {
            int col = wn * 32 + nb2 * 16 + h * 8 + cb;
            const float* f = acc + nb2 * 8 + h * 4;
            sx[r0 * 68 + col]           = f[0];
            sx[r0 * 68 + col + 1]       = f[1];
            sx[(r0 + 8) * 68 + col]     = f[2];
            sx[(r0 + 8) * 68 + col + 1] = f[3];
        }
    }
}

// ---------------- weight-row compute for one point (rigid) ----------------
#define COMPUTE_ROWS_RIGID() do {                                                \
    float qx = query[pt*3+0], qy = query[pt*3+1], qz = query[pt*3+2];            \
    idA = nbr[pt*NN + lane];                                                     \
    {                                                                            \
        float px = support[idA*3+0] - qx;                                        \
        float py = support[idA*3+1] - qy;                                        \
        float pz = support[idA*3+2] - qz;                                        \
        float wl[16]; float m = 0.f;                                             \
        _Pragma("unroll")                                                        \
        for (int k = 0; k < KP; k++) {                                           \
            float dx = px - kpts[k*3+0];                                         \
            float dy = py - kpts[k*3+1];                                         \
            float dz = pz - kpts[k*3+2];                                         \
            float sq = dx*dx + dy*dy + dz*dz;                                    \
            wl[k] = fmaxf(1.0f - 2.0f * sqrtf(sq), 0.0f);                        \
            m = fmaxf(m, wl[k]);                                                 \
        }                                                                        \
        wl[15] = 0.0f;                                                           \
        float* wr = &s_w[wid * 34 * 16 + lane * 16];                             \
        _Pragma("unroll")                                                        \
        for (int j = 0; j < 4; j++)                                              \
            *(float4*)&wr[j*4] = make_float4(wl[j*4+0], wl[j*4+1], wl[j*4+2], wl[j*4+3]); \
        mA = m;                                                                  \
    }                                                                            \
    mB = 0.f;                                                                    \
    {                                                                            \
        bool valid = (lane < 2);                                                 \
        idB = valid ? nbr[pt*NN + 32 + lane] : 0;                                \
        float px = support[idB*3+0] - qx;                                        \
        float py = support[idB*3+1] - qy;                                        \
        float pz = support[idB*3+2] - qz;                                        \
        float wl[16]; float m = 0.f;                                             \
        _Pragma("unroll")                                                        \
        for (int k = 0; k < KP; k++) {                                           \
            float dx = px - kpts[k*3+0];                                         \
            float dy = py - kpts[k*3+1];                                         \
            float dz = pz - kpts[k*3+2];                                         \
            float sq = dx*dx + dy*dy + dz*dz;                                    \
            wl[k] = fmaxf(1.0f - 2.0f * sqrtf(sq), 0.0f);                        \
            m = fmaxf(m, wl[k]);                                                 \
        }                                                                        \
        wl[15] = 0.0f;                                                           \
        if (valid) {                                                             \
            float* wr = &s_w[wid * 34 * 16 + (32 + lane) * 16];                  \
            _Pragma("unroll")                                                    \
            for (int j = 0; j < 4; j++)                                          \
                *(float4*)&wr[j*4] = make_float4(wl[j*4+0], wl[j*4+1], wl[j*4+2], wl[j*4+3]); \
            mB = m;                                                              \
        }                                                                        \
    }                                                                            \
} while (0)

#define COMPUTE_ROWS_DEF() do {                                                  \
    float qx = query[pt*3+0], qy = query[pt*3+1], qz = query[pt*3+2];            \
    idA = nbr[pt*NN + lane];                                                     \
    {                                                                            \
        float px = support[idA*3+0] - qx;                                        \
        float py = support[idA*3+1] - qy;                                        \
        float pz = support[idA*3+2] - qz;                                        \
        float wl[16]; float m = 0.f;                                             \
        _Pragma("unroll")                                                        \
        for (int k = 0; k < KP; k++) {                                           \
            const float* dk = &s_dkp[(wid * KP + k) * 4];                        \
            float dx = px - dk[0];                                               \
            float dy = py - dk[1];                                               \
            float dz = pz - dk[2];                                               \
            float sq = dx*dx + dy*dy + dz*dz;                                    \
            wl[k] = fmaxf(1.0f - 2.0f * sqrtf(sq), 0.0f);                        \
            m = fmaxf(m, wl[k]);                                                 \
        }                                                                        \
        wl[15] = 0.0f;                                                           \
        float* wr = &s_w[wid * 34 * 16 + lane * 16];                             \
        _Pragma("unroll")                                                        \
        for (int j = 0; j < 4; j++)                                              \
            *(float4*)&wr[j*4] = make_float4(wl[j*4+0], wl[j*4+1], wl[j*4+2], wl[j*4+3]); \
        mA = m;                                                                  \
    }                                                                            \
    mB = 0.f;                                                                    \
    {                                                                            \
        bool valid = (lane < 2);                                                 \
        idB = valid ? nbr[pt*NN + 32 + lane] : 0;                                \
        float px = support[idB*3+0] - qx;                                        \
        float py = support[idB*3+1] - qy;                                        \
        float pz = support[idB*3+2] - qz;                                        \
        float wl[16]; float m = 0.f;                                             \
        _Pragma("unroll")                                                        \
        for (int k = 0; k < KP; k++) {                                           \
            const float* dk = &s_dkp[(wid * KP + k) * 4];                        \
            float dx = px - dk[0];                                               \
            float dy = py - dk[1];                                               \
            float dz = pz - dk[2];                                               \
            float sq = dx*dx + dy*dy + dz*dz;                                    \
            wl[k] = fmaxf(1.0f - 2.0f * sqrtf(sq), 0.0f);                        \
            m = fmaxf(m, wl[k]);                                                 \
        }                                                                        \
        wl[15] = 0.0f;                                                           \
        if (valid) {                                                             \
            float* wr = &s_w[wid * 34 * 16 + (32 + lane) * 16];                  \
            _Pragma("unroll")                                                    \
            for (int j = 0; j < 4; j++)                                          \
                *(float4*)&wr[j*4] = make_float4(wl[j*4+0], wl[j*4+1], wl[j*4+2], wl[j*4+3]); \
            mB = m;                                                              \
        }                                                                        \
    }                                                                            \
} while (0)

#define BUILD_MASK(mask) do {                                                    \
    u32 b0 = __ballot_sync(0xffffffffu, mA > 0.f);                               \
    u32 b1 = __ballot_sync(0xffffffffu, (lane < 2) && (mB > 0.f));               \
    mask = (u64)b0 | ((u64)(b1 & 3u) << 32);                                     \
} while (0)

// ---------------- fused stage 1: rigid gather + GEMM1 -> dkp ----------------
__global__ __launch_bounds__(256, 3) void fused1_kernel(
    const float* __restrict__ query, const float* __restrict__ support,
    const int* __restrict__ nbr, const float* __restrict__ feat,
    const float* __restrict__ kpts, const float* __restrict__ obias)
{
    extern __shared__ __align__(16) char smem[];
    float* s_w = (float*)(smem + SW_OFF);

    const int tid  = threadIdx.x;
    const int wid  = tid >> 5;
    const int lane = tid & 31;
    const int pt0  = blockIdx.x * MT;

    // ===== gather phase: each warp does 8 points =====
    for (int i = 0; i < 8; i++) {
        int pt = pt0 + wid * 8 + i;
        int idA, idB; float mA, mB;
        COMPUTE_ROWS_RIGID();
        u64 mask; BUILD_MASK(mask);
        __syncwarp();

        float2 acc[8][2];
        #pragma unroll
        for (int j = 0; j < 8; j++) { acc[j][0] = make_float2(0.f,0.f); acc[j][1] = make_float2(0.f,0.f); }
        SPARSE_GATHER_LOOP(mask);
        STORE_A(pt);
        __syncwarp();
    }
    __syncthreads();

    // ===== GEMM phase =====
    float acc[16];
    run_gemm_fused(g_OB1, g_OB2, smem, acc);

    float* sx = (float*)smem;
    acc_to_smem(sx, acc);
    __syncthreads();

    if (tid < MT) {
        int n = pt0 + tid;
        float f0[60];
        #pragma unroll
        for (int i = 0; i < 60; i++) f0[i] = sx[tid * 68 + i] + obias[i];
        #pragma unroll
        for (int k = 0; k < KP; k++) {
            float4 o;
            o.x = kpts[k*3+0] + f0[3*k+0] * EXTENTF;
            o.y = kpts[k*3+1] + f0[3*k+1] * EXTENTF;
            o.z = kpts[k*3+2] + f0[3*k+2] * EXTENTF;
            o.w = 2.0f / (1.0f + expf(-f0[45 + k]));
            ((float4*)g_dkp)[n * KP + k] = o;
        }
    }
}

// ---------------- fused stage 2: deformed gather + GEMM2 -> out + BN partials ----------------
__global__ __launch_bounds__(256, 3) void fused2_kernel(
    const float* __restrict__ query, const float* __restrict__ support,
    const int* __restrict__ nbr, const float* __restrict__ feat,
    float* __restrict__ out)
{
    extern __shared__ __align__(16) char smem[];
    float* s_w   = (float*)(smem + SW_OFF);
    float* s_dkp = (float*)(smem + DKP_OFF);

    const int tid  = threadIdx.x;
    const int wid  = tid >> 5;
    const int lane = tid & 31;
    const int pt0  = blockIdx.x * MT;

    // ===== gather phase =====
    for (int i = 0; i < 8; i++) {
        int pt = pt0 + wid * 8 + i;
        if (lane < KP)
            *(float4*)&s_dkp[(wid * KP + lane) * 4] = ((const float4*)g_dkp)[pt * KP + lane];
        __syncwarp();

        int idA, idB; float mA, mB;
        COMPUTE_ROWS_DEF();
        u64 mask; BUILD_MASK(mask);
        __syncwarp();

        float2 acc[8][2];
        #pragma unroll
        for (int j = 0; j < 8; j++) { acc[j][0] = make_float2(0.f,0.f); acc[j][1] = make_float2(0.f,0.f); }
        SPARSE_GATHER_LOOP(mask);

        // apply modulations
        #pragma unroll
        for (int j = 0; j < 8; j++) {
            float mx = s_dkp[(wid * KP + 2*j) * 4 + 3];
            float my = (j < 7) ? s_dkp[(wid * KP + 2*j + 1) * 4 + 3] : 0.f;
            acc[j][0].x *= mx; acc[j][0].y *= my;
            acc[j][1].x *= mx; acc[j][1].y *= my;
        }
        STORE_A(pt);
        __syncwarp();
    }
    __syncthreads();

    // ===== GEMM phase =====
    float acc[16];
    run_gemm_fused(g_WB1, g_WB2, smem, acc);

    float* sx = (float*)smem;
    acc_to_smem(sx, acc);
    __syncthreads();

    {
        const int base4 = pt0 * (OUTF / 4);
        for (int v = tid; v < MT * OUTF / 4; v += 256) {
            int pl = v >> 4, j = v & 15;
            float4 val = *(float4*)&sx[pl * 68 + j * 4];
            ((float4*)out)[base4 + v] = val;
        }
    }
    if (tid < OUTF) {
        float s = 0.f, s2 = 0.f;
        for (int pl = 0; pl < MT; pl++) {
            float v = sx[pl * 68 + tid];
            s += v; s2 += v * v;
        }
        g_psum  [blockIdx.x * OUTF + tid] = s;
        g_psumsq[blockIdx.x * OUTF + tid] = s2;
    }
}

// ---------------- BN stats ----------------
__global__ void stats_kernel(const float* __restrict__ gamma, const float* __restrict__ beta) {
    int o = blockIdx.x;
    int tid = threadIdx.x;
    float s = 0.f, s2 = 0.f;
    for (int j = tid; j < NFUSE; j += blockDim.x) {
        s  += g_psum  [j * OUTF + o];
        s2 += g_psumsq[j * OUTF + o];
    }
    __shared__ float sh[256], sh2[256];
    sh[tid] = s; sh2[tid] = s2;
    __syncthreads();
    for (int st = 128; st > 0; st >>= 1) {
        if (tid < st) { sh[tid] += sh[tid + st]; sh2[tid] += sh2[tid + st]; }
        __syncthreads();
    }
    if (tid == 0) {
        float mean = sh[0]  / (float)NPTS;
        float var  = sh2[0] / (float)NPTS - mean * mean;
        float sc   = rsqrtf(var + 1e-6f) * gamma[o];
        g_scale[o] = sc;
        g_shift[o] = beta[o] - mean * sc;
    }
}

// ---------------- BN apply + LeakyReLU ----------------
__global__ void bn_kernel(float* __restrict__ out) {
    const int total4 = NPTS * OUTF / 4;
    for (int i = blockIdx.x * blockDim.x + threadIdx.x; i < total4; i += gridDim.x * blockDim.x) {
        float4 v = ((float4*)out)[i];
        int ch = (i & 15) * 4;
        float4 sc = *(const float4*)&g_scale[ch];
        float4 sh = *(const float4*)&g_shift[ch];
        v.x = v.x * sc.x + sh.x;  v.x = v.x >= 0.f ? v.x : 0.1f * v.x;
        v.y = v.y * sc.y + sh.y;  v.y = v.y >= 0.f ? v.y : 0.1f * v.y;
        v.z = v.z * sc.z + sh.z;  v.z = v.z >= 0.f ? v.z : 0.1f * v.z;
        v.w = v.w * sc.w + sh.w;  v.w = v.w >= 0.f ? v.w : 0.1f * v.w;
        ((float4*)out)[i] = v;
    }
}

// ---------------- launch ----------------
extern "C" void kernel_launch(void* const* d_in, const int* in_sizes, int n_in,
                              void* d_out, int out_size) {
    const float* query   = (const float*)d_in[0];
    const float* support = (const float*)d_in[1];
    const int*   nbr     = (const int*)  d_in[2];
    const float* feat    = (const float*)d_in[3];
    const float* weight  = (const float*)d_in[4];
    const float* ow      = (const float*)d_in[5];
    const float* obias   = (const float*)d_in[6];
    const float* gamma   = (const float*)d_in[7];
    const float* beta    = (const float*)d_in[8];
    const float* kpts    = (const float*)d_in[9];
    float* out = (float*)d_out;

    static int attr_set = 0;
    if (!attr_set) {
        cudaFuncSetAttribute(fused1_kernel, cudaFuncAttributeMaxDynamicSharedMemorySize, SM_FUSE);
        cudaFuncSetAttribute(fused2_kernel, cudaFuncAttributeMaxDynamicSharedMemorySize, SM_FUSE);
        attr_set = 1;
    }

    prep_kernel  <<<64, 256>>>(ow, weight);
    fused1_kernel<<<NFUSE, 256, SM_FUSE>>>(query, support, nbr, feat, kpts, obias);
    fused2_kernel<<<NFUSE, 256, SM_FUSE>>>(query, support, nbr, feat, out);
    stats_kernel <<<OUTF, 256>>>(gamma, beta);
    bn_kernel    <<<2048, 256>>>(out);
}

// round 17
// speedup vs baseline: 1.4106x; 1.4106x over previous
#include <cuda_runtime.h>
#include <cuda_bf16.h>
#include <math.h>
#include <stdint.h>

#define NPTS   65536
#define NN     34
#define KP     15
#define INF    64
#define OUTF   64
#define EXTENTF 0.5f
#define PPB    4                  // points per gather CTA (1 warp each)
#define TPB_G  128
#define NBLK_G (NPTS / PPB)       // 16384 gather CTAs
#define KW2    512                // u32 words per A/B row (bf16 pairs), K'=1024 (i' = c*16+k, k=15 pad)
#define MT     128                // GEMM tile M
#define NGEMM  (NPTS / MT)        // 512 GEMM CTAs
#define NCHUNK 16                 // 1024 / 64

// GEMM smem: padded tiles, row stride 144B (72 bf16) -> conflict-free ldmatrix
// Double-buffered: two 55296B buffers.
#define AS      144
#define OFS_A1  0
#define OFS_A2  18432
#define OFS_B1  36864
#define OFS_B2  46080
#define BUFSZ   55296
#define SM_GEMM (2 * BUFSZ)       // 110592 B

typedef unsigned long long u64;
typedef unsigned int u32;

// ---------------- device scratch ----------------
__device__ __align__(16) u32 g_A1[NPTS * KW2];    // wf hi  (bf16 pairs, i' = c*16+k)
__device__ __align__(16) u32 g_A2[NPTS * KW2];    // wf residual
__device__ __align__(16) u32 g_OB1[64 * KW2];     // offset_weight^T hi [d][i'] pairs
__device__ __align__(16) u32 g_OB2[64 * KW2];
__device__ __align__(16) u32 g_WB1[64 * KW2];     // weight^T hi [o][i'] pairs
__device__ __align__(16) u32 g_WB2[64 * KW2];
__device__ __align__(16) float g_dkp[NPTS * KP * 4];  // deformed kp xyz + modulation
__device__ float g_psum  [NGEMM * OUTF];
__device__ float g_psumsq[NGEMM * OUTF];
__device__ __align__(16) float g_scale[OUTF];
__device__ __align__(16) float g_shift[OUTF];

// ---------------- helpers ----------------
__device__ __forceinline__ void f2fma(float2 &acc, float2 a, float2 b) {
    asm("{\n\t"
        ".reg .b64 ra, rb, rc;\n\t"
        "mov.b64 ra, {%2, %3};\n\t"
        "mov.b64 rb, {%4, %5};\n\t"
        "mov.b64 rc, {%0, %1};\n\t"
        "fma.rn.f32x2 rc, ra, rb, rc;\n\t"
        "mov.b64 {%0, %1}, rc;\n\t"
        "}"
        : "+f"(acc.x), "+f"(acc.y)
        : "f"(a.x), "f"(a.y), "f"(b.x), "f"(b.y));
}

__device__ __forceinline__ uint32_t smem_u32(const void* p) {
    uint32_t a;
    asm("{ .reg .u64 t; cvta.to.shared.u64 t, %1; cvt.u32.u64 %0, t; }" : "=r"(a) : "l"(p));
    return a;
}

#define CP_ASYNC16(dst, src)                                                      \
    asm volatile("{ .reg .u64 g; cvta.to.global.u64 g, %1; "                      \
                 "cp.async.cg.shared.global [%0], [g], 16; }"                     \
                 :: "r"(dst), "l"(src) : "memory")
#define CP_COMMIT() asm volatile("cp.async.commit_group;" ::: "memory")
#define CP_WAIT0()  asm volatile("cp.async.wait_group 0;" ::: "memory")

#define LDSM_X4(r, addr)                                                          \
    asm volatile("ldmatrix.sync.aligned.m8n8.x4.shared.b16 {%0,%1,%2,%3}, [%4];"  \
        : "=r"((r)[0]), "=r"((r)[1]), "=r"((r)[2]), "=r"((r)[3]) : "r"(addr))

#define MMA_BF16(d, a, b0, b1)                                                    \
    asm volatile("mma.sync.aligned.m16n8k16.row.col.f32.bf16.bf16.f32 "           \
        "{%0,%1,%2,%3}, {%4,%5,%6,%7}, {%8,%9}, {%0,%1,%2,%3};"                   \
        : "+f"((d)[0]), "+f"((d)[1]), "+f"((d)[2]), "+f"((d)[3])                  \
        : "r"((a)[0]), "r"((a)[1]), "r"((a)[2]), "r"((a)[3]), "r"(b0), "r"(b1))

__device__ __forceinline__ u32 pack_bf16(float lo, float hi) {
    __nv_bfloat162 h = __floats2bfloat162_rn(lo, hi);
    return *(u32*)&h;
}
__device__ __forceinline__ float bf16_res(float v) {
    return v - __bfloat162float(__float2bfloat16_rn(v));
}

// ---------------- prep: hi/lo bf16 transposed weight matrices, i' = c*16+k order ----------------
__global__ void prep_kernel(const float* __restrict__ ow, const float* __restrict__ w) {
    int t = blockIdx.x * blockDim.x + threadIdx.x;
    int stride = gridDim.x * blockDim.x;
    for (int idx = t; idx < 64 * KW2; idx += stride) {
        int row = idx / KW2, j = idx - row * KW2;
        int ip0 = 2 * j, ip1 = 2 * j + 1;
        int c0 = ip0 >> 4, k0 = ip0 & 15;
        int c1 = ip1 >> 4, k1 = ip1 & 15;
        // offset_weight [i=k*64+c][d=60]
        float v0 = (k0 < 15 && row < 60) ? ow[(k0 * 64 + c0) * 60 + row] : 0.f;
        float v1 = (k1 < 15 && row < 60) ? ow[(k1 * 64 + c1) * 60 + row] : 0.f;
        g_OB1[idx] = pack_bf16(v0, v1);
        g_OB2[idx] = pack_bf16(bf16_res(v0), bf16_res(v1));
        // weight [i=k*64+c][o=64]
        float u0 = (k0 < 15) ? w[(k0 * 64 + c0) * 64 + row] : 0.f;
        float u1 = (k1 < 15) ? w[(k1 * 64 + c1) * 64 + row] : 0.f;
        g_WB1[idx] = pack_bf16(u0, u1);
        g_WB2[idx] = pack_bf16(bf16_res(u0), bf16_res(u1));
    }
}

// ---------------- gather FMA block: 16 FFMA2 on one weight row ----------------
// lane owns channels c0=2*lane (h=0) and c0+1 (h=1)
#define WROW16(a_cur, f_cur) do {                                                \
    float2 ff0 = make_float2((f_cur).x, (f_cur).x);                              \
    float2 ff1 = make_float2((f_cur).y, (f_cur).y);                              \
    const float4* wr = (const float4*)&s_w[p][a_cur][0];                         \
    float4 w0 = wr[0], w1 = wr[1], w2 = wr[2], w3 = wr[3];                       \
    f2fma(acc[0][0], make_float2(w0.x, w0.y), ff0);                              \
    f2fma(acc[0][1], make_float2(w0.x, w0.y), ff1);                              \
    f2fma(acc[1][0], make_float2(w0.z, w0.w), ff0);                              \
    f2fma(acc[1][1], make_float2(w0.z, w0.w), ff1);                              \
    f2fma(acc[2][0], make_float2(w1.x, w1.y), ff0);                              \
    f2fma(acc[2][1], make_float2(w1.x, w1.y), ff1);                              \
    f2fma(acc[3][0], make_float2(w1.z, w1.w), ff0);                              \
    f2fma(acc[3][1], make_float2(w1.z, w1.w), ff1);                              \
    f2fma(acc[4][0], make_float2(w2.x, w2.y), ff0);                              \
    f2fma(acc[4][1], make_float2(w2.x, w2.y), ff1);                              \
    f2fma(acc[5][0], make_float2(w2.z, w2.w), ff0);                              \
    f2fma(acc[5][1], make_float2(w2.z, w2.w), ff1);                              \
    f2fma(acc[6][0], make_float2(w3.x, w3.y), ff0);                              \
    f2fma(acc[6][1], make_float2(w3.x, w3.y), ff1);                              \
    f2fma(acc[7][0], make_float2(w3.z, w3.w), ff0);                              \
    f2fma(acc[7][1], make_float2(w3.z, w3.w), ff1);                              \
} while (0)

// sparse gather loop over compacted nonzero-row list, depth-2 prefetch
#define SPARSE_GATHER_LOOP() do {                                                \
    if (cnt > 0) {                                                               \
        int a_p0 = s_list[p][0];                                                 \
        float2 f_p0 = *(const float2*)&feat[(size_t)s_idx[p][a_p0] * INF + 2 * lane]; \
        int a_p1 = 0; float2 f_p1 = make_float2(0.f, 0.f);                       \
        if (cnt > 1) {                                                           \
            a_p1 = s_list[p][1];                                                 \
            f_p1 = *(const float2*)&feat[(size_t)s_idx[p][a_p1] * INF + 2 * lane]; \
        }                                                                        \
        for (int i = 0; i < cnt; i++) {                                          \
            int a_cur = a_p0; float2 f_cur = f_p0;                               \
            a_p0 = a_p1; f_p0 = f_p1;                                            \
            if (i + 2 < cnt) {                                                   \
                a_p1 = s_list[p][i + 2];                                         \
                f_p1 = *(const float2*)&feat[(size_t)s_idx[p][a_p1] * INF + 2 * lane]; \
            }                                                                    \
            WROW16(a_cur, f_cur);                                                \
        }                                                                        \
    }                                                                            \
} while (0)

// direct bf16 hi/res pack + store: lane writes 8 pairs per channel (c = 2*lane+h)
#define STORE_A(nn) do {                                                         \
    _Pragma("unroll")                                                            \
    for (int h = 0; h < 2; h++) {                                                \
        int c = 2 * lane + h;                                                    \
        u32 base = (u32)(nn) * KW2 + (u32)c * 8;                                 \
        uint4 hi0, hi1, lo0, lo1;                                                \
        hi0.x = pack_bf16(acc[0][h].x, acc[0][h].y);                             \
        hi0.y = pack_bf16(acc[1][h].x, acc[1][h].y);                             \
        hi0.z = pack_bf16(acc[2][h].x, acc[2][h].y);                             \
        hi0.w = pack_bf16(acc[3][h].x, acc[3][h].y);                             \
        hi1.x = pack_bf16(acc[4][h].x, acc[4][h].y);                             \
        hi1.y = pack_bf16(acc[5][h].x, acc[5][h].y);                             \
        hi1.z = pack_bf16(acc[6][h].x, acc[6][h].y);                             \
        hi1.w = pack_bf16(acc[7][h].x, acc[7][h].y);                             \
        lo0.x = pack_bf16(bf16_res(acc[0][h].x), bf16_res(acc[0][h].y));         \
        lo0.y = pack_bf16(bf16_res(acc[1][h].x), bf16_res(acc[1][h].y));         \
        lo0.z = pack_bf16(bf16_res(acc[2][h].x), bf16_res(acc[2][h].y));         \
        lo0.w = pack_bf16(bf16_res(acc[3][h].x), bf16_res(acc[3][h].y));         \
        lo1.x = pack_bf16(bf16_res(acc[4][h].x), bf16_res(acc[4][h].y));         \
        lo1.y = pack_bf16(bf16_res(acc[5][h].x), bf16_res(acc[5][h].y));         \
        lo1.z = pack_bf16(bf16_res(acc[6][h].x), bf16_res(acc[6][h].y));         \
        lo1.w = pack_bf16(bf16_res(acc[7][h].x), bf16_res(acc[7][h].y));         \
        *(uint4*)&g_A1[base]     = hi0;                                          \
        *(uint4*)&g_A1[base + 4] = hi1;                                          \
        *(uint4*)&g_A2[base]     = lo0;                                          \
        *(uint4*)&g_A2[base + 4] = lo1;                                          \
    }                                                                            \
} while (0)

// build compact list of nonzero rows from row-max values mA (a=lane) and mB (a=lane+32, lanes 0/1)
#define BUILD_LIST() do {                                                        \
    u32 b0 = __ballot_sync(0xffffffffu, mA > 0.f);                               \
    u32 b1 = __ballot_sync(0xffffffffu, (lane < 2) && (mB > 0.f));               \
    u32 below = (lane == 0) ? 0u : (0xffffffffu >> (32 - lane));                 \
    int posA = __popc(b0 & below);                                               \
    if (mA > 0.f) s_list[p][posA] = lane;                                        \
    int baseB = __popc(b0);                                                      \
    if ((lane < 2) && (mB > 0.f))                                                \
        s_list[p][baseB + __popc(b1 & below)] = lane + 32;                       \
    cnt = baseB + __popc(b1);                                                    \
} while (0)

// ---------------- gather 1: rigid weights -> wf0 -> A (bf16 split) ----------------
__global__ __launch_bounds__(TPB_G, 6) void gather1_kernel(
    const float* __restrict__ query, const float* __restrict__ support,
    const int* __restrict__ nbr, const float* __restrict__ feat,
    const float* __restrict__ kpts)
{
    __shared__ __align__(16) float s_w [PPB][NN][20];
    __shared__ int                 s_idx[PPB][NN];
    __shared__ int                 s_list[PPB][NN + 2];

    const int tid  = threadIdx.x;
    const int p    = tid >> 5;
    const int lane = tid & 31;
    const int n    = blockIdx.x * PPB + p;
    int cnt;

    {
        float qx = query[n*3+0], qy = query[n*3+1], qz = query[n*3+2];
        // row A: a = lane
        float mA;
        {
            int id = nbr[n*NN + lane];
            s_idx[p][lane] = id;
            float px = support[id*3+0] - qx;
            float py = support[id*3+1] - qy;
            float pz = support[id*3+2] - qz;
            float wl[16]; float m = 0.f;
            #pragma unroll
            for (int k = 0; k < KP; k++) {
                float dx = px - kpts[k*3+0];
                float dy = py - kpts[k*3+1];
                float dz = pz - kpts[k*3+2];
                float sq = dx*dx + dy*dy + dz*dz;
                wl[k] = fmaxf(1.0f - 2.0f * sqrtf(sq), 0.0f);
                m = fmaxf(m, wl[k]);
            }
            wl[15] = 0.0f;
            #pragma unroll
            for (int j = 0; j < 4; j++)
                *(float4*)&s_w[p][lane][j*4] = make_float4(wl[j*4+0], wl[j*4+1], wl[j*4+2], wl[j*4+3]);
            mA = m;
        }
        // row B: a = lane+32 (valid lanes 0,1)
        float mB = 0.f;
        {
            bool valid = (lane < 2);
            int id = valid ? nbr[n*NN + 32 + lane] : 0;
            float px = support[id*3+0] - qx;
            float py = support[id*3+1] - qy;
            float pz = support[id*3+2] - qz;
            float wl[16]; float m = 0.f;
            #pragma unroll
            for (int k = 0; k < KP; k++) {
                float dx = px - kpts[k*3+0];
                float dy = py - kpts[k*3+1];
                float dz = pz - kpts[k*3+2];
                float sq = dx*dx + dy*dy + dz*dz;
                wl[k] = fmaxf(1.0f - 2.0f * sqrtf(sq), 0.0f);
                m = fmaxf(m, wl[k]);
            }
            wl[15] = 0.0f;
            if (valid) {
                s_idx[p][32 + lane] = id;
                #pragma unroll
                for (int j = 0; j < 4; j++)
                    *(float4*)&s_w[p][32 + lane][j*4] = make_float4(wl[j*4+0], wl[j*4+1], wl[j*4+2], wl[j*4+3]);
                mB = m;
            }
        }
        BUILD_LIST();
    }
    __syncwarp();

    float2 acc[8][2];
    #pragma unroll
    for (int j = 0; j < 8; j++) { acc[j][0] = make_float2(0.f,0.f); acc[j][1] = make_float2(0.f,0.f); }

    SPARSE_GATHER_LOOP();
    STORE_A(n);
}

// ---------------- gather 2: deformed weights (+mod) -> wf -> A (bf16 split) ----------------
__global__ __launch_bounds__(TPB_G, 6) void gather2_kernel(
    const float* __restrict__ query, const float* __restrict__ support,
    const int* __restrict__ nbr, const float* __restrict__ feat)
{
    __shared__ __align__(16) float s_w  [PPB][NN][20];
    __shared__ int                 s_idx[PPB][NN];
    __shared__ int                 s_list[PPB][NN + 2];
    __shared__ __align__(16) float s_dkp[PPB][KP][4];

    const int tid  = threadIdx.x;
    const int p    = tid >> 5;
    const int lane = tid & 31;
    const int n    = blockIdx.x * PPB + p;
    int cnt;

    if (lane < KP)
        *(float4*)&s_dkp[p][lane][0] = ((const float4*)g_dkp)[n * KP + lane];
    __syncwarp();

    {
        float qx = query[n*3+0], qy = query[n*3+1], qz = query[n*3+2];
        float mA;
        {
            int id = nbr[n*NN + lane];
            s_idx[p][lane] = id;
            float px = support[id*3+0] - qx;
            float py = support[id*3+1] - qy;
            float pz = support[id*3+2] - qz;
            float wl[16]; float m = 0.f;
            #pragma unroll
            for (int k = 0; k < KP; k++) {
                float dx = px - s_dkp[p][k][0];
                float dy = py - s_dkp[p][k][1];
                float dz = pz - s_dkp[p][k][2];
                float sq = dx*dx + dy*dy + dz*dz;
                wl[k] = fmaxf(1.0f - 2.0f * sqrtf(sq), 0.0f);
                m = fmaxf(m, wl[k]);
            }
            wl[15] = 0.0f;
            #pragma unroll
            for (int j = 0; j < 4; j++)
                *(float4*)&s_w[p][lane][j*4] = make_float4(wl[j*4+0], wl[j*4+1], wl[j*4+2], wl[j*4+3]);
            mA = m;
        }
        float mB = 0.f;
        {
            bool valid = (lane < 2);
            int id = valid ? nbr[n*NN + 32 + lane] : 0;
            float px = support[id*3+0] - qx;
            float py = support[id*3+1] - qy;
            float pz = support[id*3+2] - qz;
            float wl[16]; float m = 0.f;
            #pragma unroll
            for (int k = 0; k < KP; k++) {
                float dx = px - s_dkp[p][k][0];
                float dy = py - s_dkp[p][k][1];
                float dz = pz - s_dkp[p][k][2];
                float sq = dx*dx + dy*dy + dz*dz;
                wl[k] = fmaxf(1.0f - 2.0f * sqrtf(sq), 0.0f);
                m = fmaxf(m, wl[k]);
            }
            wl[15] = 0.0f;
            if (valid) {
                s_idx[p][32 + lane] = id;
                #pragma unroll
                for (int j = 0; j < 4; j++)
                    *(float4*)&s_w[p][32 + lane][j*4] = make_float4(wl[j*4+0], wl[j*4+1], wl[j*4+2], wl[j*4+3]);
                mB = m;
            }
        }
        BUILD_LIST();
    }
    __syncwarp();

    float2 acc[8][2];
    #pragma unroll
    for (int j = 0; j < 8; j++) { acc[j][0] = make_float2(0.f,0.f); acc[j][1] = make_float2(0.f,0.f); }

    SPARSE_GATHER_LOOP();

    // apply modulations: acc[j][h] holds k-pairs (2j, 2j+1) for channel 2*lane+h
    #pragma unroll
    for (int j = 0; j < 8; j++) {
        float mx = s_dkp[p][2*j][3];
        float my = (j < 7) ? s_dkp[p][2*j+1][3] : 0.f;
        acc[j][0].x *= mx; acc[j][0].y *= my;
        acc[j][1].x *= mx; acc[j][1].y *= my;
    }
    STORE_A(n);
}

// ---------------- GEMM staging: cp.async one K-chunk into buffer ----------------
__device__ __forceinline__ void stage_chunk(const u32* __restrict__ B1g,
                                            const u32* __restrict__ B2g,
                                            int c, uint32_t smb, int buf,
                                            int tid, int pt0) {
    uint32_t base = smb + (uint32_t)buf * BUFSZ;
    #pragma unroll
    for (int it = 0; it < 4; it++) {
        int u = it * 256 + tid;
        int r = u >> 3, q = u & 7;
        uint32_t d = base + (uint32_t)(r * AS + q * 16);
        CP_ASYNC16(d + OFS_A1, g_A1 + (size_t)(pt0 + r) * KW2 + c * 32 + q * 4);
        CP_ASYNC16(d + OFS_A2, g_A2 + (size_t)(pt0 + r) * KW2 + c * 32 + q * 4);
    }
    #pragma unroll
    for (int it = 0; it < 2; it++) {
        int u = it * 256 + tid;
        int r = u >> 3, q = u & 7;
        uint32_t d = base + (uint32_t)(r * AS + q * 16);
        CP_ASYNC16(d + OFS_B1, B1g + r * KW2 + c * 32 + q * 4);
        CP_ASYNC16(d + OFS_B2, B2g + r * KW2 + c * 32 + q * 4);
    }
}

// ---------------- warp-MMA GEMM mainloop (double-buffered cp.async) ----------------
// D[128 x 64] = A[128 x 1024] * B[64 x 1024]^T, bf16 3-product split, 16 chunks of 64.
// pt0 passed in (block order reversed by caller for L2 reuse of freshly-written A).
__device__ __forceinline__ void run_gemm_wm(const u32* __restrict__ B1g,
                                            const u32* __restrict__ B2g,
                                            char* smem, float* acc, int pt0) {
    const int tid  = threadIdx.x;
    const int wid  = tid >> 5;
    const int lane = tid & 31;
    const uint32_t smb = smem_u32(smem);

    const uint32_t aoff = (uint32_t)(wid * 16 + (lane & 15)) * AS + ((lane >> 4) << 4);
    const uint32_t brow = (uint32_t)(((lane >> 4) << 3) + (lane & 7));
    const uint32_t boff = brow * AS + (((lane >> 3) & 1) << 4);

    #pragma unroll
    for (int i = 0; i < 32; i++) acc[i] = 0.f;

    stage_chunk(B1g, B2g, 0, smb, 0, tid, pt0);
    CP_COMMIT();

    int buf = 0;
    #pragma unroll 1
    for (int c = 0; c < NCHUNK; c++) {
        CP_WAIT0();
        __syncthreads();
        if (c + 1 < NCHUNK) {
            stage_chunk(B1g, B2g, c + 1, smb, buf ^ 1, tid, pt0);
            CP_COMMIT();
        }
        const uint32_t base = smb + (uint32_t)buf * BUFSZ;
        const uint32_t a1b = base + OFS_A1, a2b = base + OFS_A2;
        const uint32_t b1b = base + OFS_B1, b2b = base + OFS_B2;

        #pragma unroll
        for (int ks = 0; ks < 4; ks++) {
            const uint32_t kb = (uint32_t)(ks * 32);
            uint32_t a1[4], a2[4];
            LDSM_X4(a1, a1b + aoff + kb);
            LDSM_X4(a2, a2b + aoff + kb);
            #pragma unroll
            for (int nb2 = 0; nb2 < 4; nb2++) {
                uint32_t b1[4], b2[4];
                uint32_t bo = (uint32_t)(nb2 * 16) * AS + boff + kb;
                LDSM_X4(b1, b1b + bo);
                LDSM_X4(b2, b2b + bo);
                float* d0 = acc + (nb2 * 2) * 4;
                float* d1 = acc + (nb2 * 2 + 1) * 4;
                MMA_BF16(d0, a1, b1[0], b1[1]);
                MMA_BF16(d1, a1, b1[2], b1[3]);
                MMA_BF16(d0, a1, b2[0], b2[1]);
                MMA_BF16(d1, a1, b2[2], b2[3]);
                MMA_BF16(d0, a2, b1[0], b1[1]);
                MMA_BF16(d1, a2, b1[2], b1[3]);
            }
        }
        buf ^= 1;
    }
    __syncthreads();   // all warps done with smem before epilogue reuse
}

__device__ __forceinline__ void acc_to_smem(float* sx, const float* acc) {
    const int tid  = threadIdx.x;
    const int wid  = tid >> 5;
    const int lane = tid & 31;
    int r0 = wid * 16 + (lane >> 2);
    int cb = (lane & 3) * 2;
    #pragma unroll
    for (int nb = 0; nb < 8; nb++) {
        int col = nb * 8 + cb;
        sx[r0 * 68 + col]           = acc[nb * 4 + 0];
        sx[r0 * 68 + col + 1]       = acc[nb * 4 + 1];
        sx[(r0 + 8) * 68 + col]     = acc[nb * 4 + 2];
        sx[(r0 + 8) * 68 + col + 1] = acc[nb * 4 + 3];
    }
}

// ---------------- GEMM 1: f0 -> deformed kernel points + modulations ----------------
__global__ __launch_bounds__(256, 1) void gemm1_kernel(
    const float* __restrict__ obias, const float* __restrict__ kpts) {
    extern __shared__ __align__(16) char smem[];
    const int bid = NGEMM - 1 - blockIdx.x;   // reversed order: read tail of A (L2-resident)
    const int pt0 = bid * MT;
    float acc[32];
    run_gemm_wm(g_OB1, g_OB2, smem, acc, pt0);

    float* sx = (float*)smem;
    acc_to_smem(sx, acc);
    __syncthreads();

    const int tid = threadIdx.x;
    if (tid < MT) {
        int n = pt0 + tid;
        float f0[60];
        #pragma unroll
        for (int i = 0; i < 60; i++) f0[i] = sx[tid * 68 + i] + obias[i];
        #pragma unroll
        for (int k = 0; k < KP; k++) {
            float4 o;
            o.x = kpts[k*3+0] + f0[3*k+0] * EXTENTF;
            o.y = kpts[k*3+1] + f0[3*k+1] * EXTENTF;
            o.z = kpts[k*3+2] + f0[3*k+2] * EXTENTF;
            o.w = 2.0f / (1.0f + expf(-f0[45 + k]));
            ((float4*)g_dkp)[n * KP + k] = o;
        }
    }
}

// ---------------- GEMM 2: x -> out + BN partials ----------------
__global__ __launch_bounds__(256, 1) void gemm2_kernel(float* __restrict__ out) {
    extern __shared__ __align__(16) char smem[];
    const int bid = NGEMM - 1 - blockIdx.x;   // reversed order
    const int pt0 = bid * MT;
    float acc[32];
    run_gemm_wm(g_WB1, g_WB2, smem, acc, pt0);

    float* sx = (float*)smem;
    acc_to_smem(sx, acc);
    __syncthreads();

    const int tid = threadIdx.x;
    {
        const int base4 = pt0 * (OUTF / 4);
        for (int v = tid; v < MT * OUTF / 4; v += 256) {
            int pl = v >> 4, j = v & 15;
            float4 val = *(float4*)&sx[pl * 68 + j * 4];
            ((float4*)out)[base4 + v] = val;
        }
    }
    if (tid < OUTF) {
        float s = 0.f, s2 = 0.f;
        for (int pl = 0; pl < MT; pl++) {
            float v = sx[pl * 68 + tid];
            s += v; s2 += v * v;
        }
        g_psum  [bid * OUTF + tid] = s;
        g_psumsq[bid * OUTF + tid] = s2;
    }
}

// ---------------- BN stats ----------------
__global__ void stats_kernel(const float* __restrict__ gamma, const float* __restrict__ beta) {
    int o = blockIdx.x;
    int tid = threadIdx.x;
    float s = 0.f, s2 = 0.f;
    for (int j = tid; j < NGEMM; j += blockDim.x) {
        s  += g_psum  [j * OUTF + o];
        s2 += g_psumsq[j * OUTF + o];
    }
    __shared__ float sh[256], sh2[256];
    sh[tid] = s; sh2[tid] = s2;
    __syncthreads();
    for (int st = 128; st > 0; st >>= 1) {
        if (tid < st) { sh[tid] += sh[tid + st]; sh2[tid] += sh2[tid + st]; }
        __syncthreads();
    }
    if (tid == 0) {
        float mean = sh[0]  / (float)NPTS;
        float var  = sh2[0] / (float)NPTS - mean * mean;
        float sc   = rsqrtf(var + 1e-6f) * gamma[o];
        g_scale[o] = sc;
        g_shift[o] = beta[o] - mean * sc;
    }
}

// ---------------- BN apply + LeakyReLU ----------------
__global__ void bn_kernel(float* __restrict__ out) {
    const int total4 = NPTS * OUTF / 4;
    for (int i = blockIdx.x * blockDim.x + threadIdx.x; i < total4; i += gridDim.x * blockDim.x) {
        float4 v = ((float4*)out)[i];
        int ch = (i & 15) * 4;
        float4 sc = *(const float4*)&g_scale[ch];
        float4 sh = *(const float4*)&g_shift[ch];
        v.x = v.x * sc.x + sh.x;  v.x = v.x >= 0.f ? v.x : 0.1f * v.x;
        v.y = v.y * sc.y + sh.y;  v.y = v.y >= 0.f ? v.y : 0.1f * v.y;
        v.z = v.z * sc.z + sh.z;  v.z = v.z >= 0.f ? v.z : 0.1f * v.z;
        v.w = v.w * sc.w + sh.w;  v.w = v.w >= 0.f ? v.w : 0.1f * v.w;
        ((float4*)out)[i] = v;
    }
}

// ---------------- launch ----------------
extern "C" void kernel_launch(void* const* d_in, const int* in_sizes, int n_in,
                              void* d_out, int out_size) {
    const float* query   = (const float*)d_in[0];
    const float* support = (const float*)d_in[1];
    const int*   nbr     = (const int*)  d_in[2];
    const float* feat    = (const float*)d_in[3];
    const float* weight  = (const float*)d_in[4];
    const float* ow      = (const float*)d_in[5];
    const float* obias   = (const float*)d_in[6];
    const float* gamma   = (const float*)d_in[7];
    const float* beta    = (const float*)d_in[8];
    const float* kpts    = (const float*)d_in[9];
    float* out = (float*)d_out;

    static int attr_set = 0;
    if (!attr_set) {
        cudaFuncSetAttribute(gemm1_kernel, cudaFuncAttributeMaxDynamicSharedMemorySize, SM_GEMM);
        cudaFuncSetAttribute(gemm2_kernel, cudaFuncAttributeMaxDynamicSharedMemorySize, SM_GEMM);
        attr_set = 1;
    }

    prep_kernel   <<<64, 256>>>(ow, weight);
    gather1_kernel<<<NBLK_G, TPB_G>>>(query, support, nbr, feat, kpts);
    gemm1_kernel  <<<NGEMM, 256, SM_GEMM>>>(obias, kpts);
    gather2_kernel<<<NBLK_G, TPB_G>>>(query, support, nbr, feat);
    gemm2_kernel  <<<NGEMM, 256, SM_GEMM>>>(out);
    stats_kernel  <<<OUTF, 256>>>(gamma, beta);
    bn_kernel     <<<2048, 256>>>(out);
}